// round 12
// baseline (speedup 1.0000x reference)
#include <cuda_runtime.h>
#include <cuda_bf16.h>
#include <cstdint>

#define FULL 0xffffffffu

constexpr int Bn = 16, Hn = 128, Wn = 128, Sn = 4, Cn = 64;
constexpr int SCn = Sn * Cn;                // 256
constexpr int NPIX = Bn * Hn * Wn;          // 262144

// Scratch (static device arrays -- allocation-free rule)
__device__ __nv_bfloat16 g_xpb[(size_t)NPIX * 128];        // [pix][hi(64)|lo(64)] bf16
__device__ __align__(16) float g_hpost[(size_t)NPIX * Sn]; // [pix][4]
__device__ __align__(16) float g_hres[(size_t)NPIX * 16];  // [pix][16] (sinkhorn'd)
__device__ __nv_bfloat16 g_wb[6 * 64 * 192];               // conv W: [ky*2+var][co][k=(kx,ci)=192]
__device__ __nv_bfloat16 g_wpj[2 * 32 * 256];              // proj W: [var][o(32)][k=256]

union F2U { float2 f; unsigned long long u; };

__device__ __forceinline__ uint32_t smem_u32(const void* p) {
    uint32_t a;
    asm("{ .reg .u64 t; cvta.to.shared.u64 t, %1; cvt.u32.u64 %0, t; }" : "=r"(a) : "l"(p));
    return a;
}
__device__ __forceinline__ void ldsm4(uint32_t& r0, uint32_t& r1, uint32_t& r2, uint32_t& r3, uint32_t addr) {
    asm volatile("ldmatrix.sync.aligned.m8n8.x4.shared.b16 {%0,%1,%2,%3}, [%4];"
                 : "=r"(r0), "=r"(r1), "=r"(r2), "=r"(r3) : "r"(addr));
}
__device__ __forceinline__ void mma16816(float* d, uint32_t a0, uint32_t a1, uint32_t a2, uint32_t a3,
                                         uint32_t b0, uint32_t b1) {
    asm volatile("mma.sync.aligned.m16n8k16.row.col.f32.bf16.bf16.f32 "
                 "{%0,%1,%2,%3}, {%4,%5,%6,%7}, {%8,%9}, {%0,%1,%2,%3};"
                 : "+f"(d[0]), "+f"(d[1]), "+f"(d[2]), "+f"(d[3])
                 : "r"(a0), "r"(a1), "r"(a2), "r"(a3), "r"(b0), "r"(b1));
}
__device__ __forceinline__ void cp16(uint32_t smaddr, const void* g) {
    asm volatile("cp.async.cg.shared.global [%0], [%1], 16;" :: "r"(smaddr), "l"(g));
}
#define CP_COMMIT() asm volatile("cp.async.commit_group;" ::: "memory")
#define CP_WAIT0()  asm volatile("cp.async.wait_group 0;" ::: "memory")
#define CP_WAIT1()  asm volatile("cp.async.wait_group 1;" ::: "memory")

// ---------------------------------------------------------------------------
// Kernel 0a: conv weight prep (unchanged)
// ---------------------------------------------------------------------------
__global__ void wprep_kernel(const float* __restrict__ conv_w)
{
    const int e = blockIdx.x * 256 + threadIdx.x;
    if (e >= 6 * 64 * 192) return;
    const int tile = e / (64 * 192);
    const int rem = e - tile * (64 * 192);
    const int co = rem / 192, k = rem - co * 192;
    const int ky = tile >> 1, var = tile & 1;
    const int kx = k >> 6, ci = k & 63;
    const float w = conv_w[((size_t)(ky * 3 + kx) * 64 + ci) * 64 + co];
    const __nv_bfloat16 hi = __float2bfloat16(w);
    __nv_bfloat16 v = hi;
    if (var) v = __float2bfloat16(w - __bfloat162float(hi));
    g_wb[e] = v;
}

// ---------------------------------------------------------------------------
// Kernel 0b: proj weight prep: g_wpj[var][o][k], o: 0..3 pre, 4..19 res,
// 20..23 post, 24..31 zero. alpha & rms_w folded; var0=hi, var1=lo.
// ---------------------------------------------------------------------------
__global__ void wprep2_kernel(
    const float* __restrict__ w_pre, const float* __restrict__ w_post, const float* __restrict__ w_res,
    const float* __restrict__ a_pre, const float* __restrict__ a_res, const float* __restrict__ a_post,
    const float* __restrict__ rms_w)
{
    const int e = blockIdx.x * 256 + threadIdx.x;      // 0 .. 16383
    if (e >= 2 * 32 * 256) return;
    const int var = e >> 13, rem = e & 8191;
    const int o = rem >> 8, k = rem & 255;
    float w = 0.f;
    if (o < 4)        w = a_pre[0]  * w_pre[o * 256 + k];
    else if (o < 20)  w = a_res[0]  * w_res[(o - 4) * 256 + k];
    else if (o < 24)  w = a_post[0] * w_post[(o - 20) * 256 + k];
    w *= rms_w[k];
    const __nv_bfloat16 hi = __float2bfloat16(w);
    g_wpj[e] = var ? __float2bfloat16(w - __bfloat162float(hi)) : hi;
}

// ---------------------------------------------------------------------------
// Kernel 1: proj via mma.sync. CTA = 64 px, 8 warps = 4 M16 x 2 N16.
// A = x bf16 hi|lo [64][512] (stride 1040B), W = [32][256] hi & lo tiles.
// Passes: xh*Wh + xl*Wh + xh*Wl (lo*lo dropped). Then gates/Sinkhorn/x_pre.
// ---------------------------------------------------------------------------
constexpr int PJ_AR = 1040;                 // A row bytes (65 x 16B)
constexpr int PJ_A  = 64 * PJ_AR;           // 66560
constexpr int PJ_WR = 528;                  // W row bytes (33 x 16B)
constexpr int PJ_W  = 64 * PJ_WR;           // 33792 (rows 0..31 Wh, 32..63 Wl)
constexpr int PJ_WL = 32 * PJ_WR;           // Wl offset 16896
constexpr int PROJ_SMEM = PJ_A + PJ_W;      // 100352

__global__ void __launch_bounds__(256, 2) proj_kernel(
    const float* __restrict__ x,
    const float* __restrict__ b_pre, const float* __restrict__ b_res, const float* __restrict__ b_post)
{
    extern __shared__ __align__(16) float dsm[];
    const uint32_t sa = smem_u32(dsm);
    const uint32_t sw = sa + PJ_A;
    __shared__ float b_all[24];
    __shared__ __align__(16) float s_hp[64][4];

    const int tid = threadIdx.x;
    if (tid < 24)
        b_all[tid] = (tid < 4) ? b_pre[tid] : (tid < 20) ? b_res[tid - 4] : b_post[tid - 20];

    const size_t pixbase = (size_t)blockIdx.x * 64;

    // ---- W tiles via cp.async (64 rows x 512B payload) ----
#pragma unroll
    for (int i = 0; i < 8; i++) {
        const int e = tid + i * 256;
        const int row = e >> 5, q = e & 31;
        cp16(sw + row * PJ_WR + q * 16, g_wpj + row * 256 + q * 8);
    }
    CP_COMMIT();

    // ---- conversion: x -> A bf16 hi|lo (coalesced LDG.128 -> STS.64) ----
    {
        const float* xb = x + pixbase * SCn;
        char* ab = reinterpret_cast<char*>(dsm);
#pragma unroll
        for (int i = 0; i < 16; i++) {
            const int e = tid + i * 256;
            const int f4 = e & 63, px = e >> 6;
            const float4 v = *reinterpret_cast<const float4*>(xb + px * SCn + f4 * 4);
            const __nv_bfloat16 hx = __float2bfloat16(v.x), hy = __float2bfloat16(v.y);
            const __nv_bfloat16 hz = __float2bfloat16(v.z), hw = __float2bfloat16(v.w);
            uint2 uh, ul;
            uh.x = (uint32_t)__bfloat16_as_ushort(hx) | ((uint32_t)__bfloat16_as_ushort(hy) << 16);
            uh.y = (uint32_t)__bfloat16_as_ushort(hz) | ((uint32_t)__bfloat16_as_ushort(hw) << 16);
            const __nv_bfloat16 lx = __float2bfloat16(v.x - __bfloat162float(hx));
            const __nv_bfloat16 ly = __float2bfloat16(v.y - __bfloat162float(hy));
            const __nv_bfloat16 lz = __float2bfloat16(v.z - __bfloat162float(hz));
            const __nv_bfloat16 lw = __float2bfloat16(v.w - __bfloat162float(hw));
            ul.x = (uint32_t)__bfloat16_as_ushort(lx) | ((uint32_t)__bfloat16_as_ushort(ly) << 16);
            ul.y = (uint32_t)__bfloat16_as_ushort(lz) | ((uint32_t)__bfloat16_as_ushort(lw) << 16);
            char* arow = ab + px * PJ_AR + f4 * 8;
            *reinterpret_cast<uint2*>(arow)       = uh;
            *reinterpret_cast<uint2*>(arow + 512) = ul;
        }
    }
    CP_WAIT0();
    __syncthreads();

    // ---- MMA: D[64][32] = A * W^T over 3 passes ----
    const int wid = tid >> 5, lane = tid & 31;
    const int wm = wid & 3, wn = wid >> 2;
    float d[2][4];
#pragma unroll
    for (int t = 0; t < 2; t++)
#pragma unroll
        for (int j = 0; j < 4; j++) d[t][j] = 0.f;

    const uint32_t a_lane = sa + (uint32_t)((16 * wm + (lane & 15)) * PJ_AR) + (uint32_t)((lane >> 4) << 4);
    const uint32_t b_lane = sw + (uint32_t)((16 * wn + (lane & 7) + ((lane >> 4) << 3)) * PJ_WR)
                               + (uint32_t)(((lane >> 3) & 1) << 4);

    const uint32_t aoffs[3] = {0u, 512u, 0u};
    const uint32_t woffs[3] = {0u, 0u, (uint32_t)PJ_WL};
#pragma unroll
    for (int pass = 0; pass < 3; pass++) {
        const uint32_t ab2 = a_lane + aoffs[pass];
        const uint32_t bb2 = b_lane + woffs[pass];
#pragma unroll
        for (int j = 0; j < 16; j++) {
            uint32_t a0, a1, a2, a3, b0, b1, b2, b3;
            ldsm4(a0, a1, a2, a3, ab2 + j * 32);
            ldsm4(b0, b1, b2, b3, bb2 + j * 32);
            mma16816(d[0], a0, a1, a2, a3, b0, b1);
            mma16816(d[1], a0, a1, a2, a3, b2, b3);
        }
    }
    __syncthreads();

    // ---- D -> s_d [64][36] (overlay A region) ----
    float* s_d = dsm;
    {
        const int gid = lane >> 2, tig = lane & 3;
#pragma unroll
        for (int t = 0; t < 2; t++) {
            const int row0 = 16 * wm + gid;
            const int col = 16 * wn + 8 * t + 2 * tig;
            *reinterpret_cast<float2*>(s_d + row0 * 36 + col)       = make_float2(d[t][0], d[t][1]);
            *reinterpret_cast<float2*>(s_d + (row0 + 8) * 36 + col) = make_float2(d[t][2], d[t][3]);
        }
    }
    __syncthreads();

    // ---- gates + Sinkhorn: one thread per pixel (tid < 64) ----
    if (tid < 64) {
        const int p = tid;
        const size_t pix = pixbase + p;

        // ss from global x (L1/L2 warm from conversion)
        const float4* xq = reinterpret_cast<const float4*>(x + pix * SCn);
        float a0 = 0.f, a1 = 0.f, a2 = 0.f, a3 = 0.f;
#pragma unroll 8
        for (int i = 0; i < 16; i++) {
            const float4 v0 = xq[i * 4 + 0], v1 = xq[i * 4 + 1];
            const float4 v2 = xq[i * 4 + 2], v3 = xq[i * 4 + 3];
            a0 += v0.x * v0.x + v0.y * v0.y + v0.z * v0.z + v0.w * v0.w;
            a1 += v1.x * v1.x + v1.y * v1.y + v1.z * v1.z + v1.w * v1.w;
            a2 += v2.x * v2.x + v2.y * v2.y + v2.z * v2.z + v2.w * v2.w;
            a3 += v3.x * v3.x + v3.y * v3.y + v3.z * v3.z + v3.w * v3.w;
        }
        const float ss = (a0 + a1) + (a2 + a3);
        const float rms = rsqrtf(ss * (1.0f / 256.0f) + 1.1920929e-07f);

        float s24[24];
#pragma unroll
        for (int j = 0; j < 24; j++) s24[j] = s_d[p * 36 + j];

#pragma unroll
        for (int s = 0; s < 4; s++)
            s_hp[p][s] = __fdividef(1.0f, 1.0f + __expf(-(s24[s] * rms + b_all[s])));
        {
            float4 hq;
            hq.x = __fdividef(2.0f, 1.0f + __expf(-(s24[20] * rms + b_all[20])));
            hq.y = __fdividef(2.0f, 1.0f + __expf(-(s24[21] * rms + b_all[21])));
            hq.z = __fdividef(2.0f, 1.0f + __expf(-(s24[22] * rms + b_all[22])));
            hq.w = __fdividef(2.0f, 1.0f + __expf(-(s24[23] * rms + b_all[23])));
            *reinterpret_cast<float4*>(g_hpost + pix * 4) = hq;
        }

        float v[16];
#pragma unroll
        for (int j = 0; j < 16; j++) v[j] = s24[4 + j] * rms + b_all[4 + j];
        float m = v[0];
#pragma unroll
        for (int j = 1; j < 16; j++) m = fmaxf(m, v[j]);
#pragma unroll
        for (int j = 0; j < 16; j++) v[j] = __expf(v[j] - m);
#pragma unroll 1
        for (int it = 0; it < 20; ++it) {
#pragma unroll
            for (int t = 0; t < 4; t++) {
                const float cs = v[t] + v[4 + t] + v[8 + t] + v[12 + t];
                const float inv = __fdividef(1.0f, cs + 1e-6f);
                v[t] *= inv; v[4 + t] *= inv; v[8 + t] *= inv; v[12 + t] *= inv;
            }
#pragma unroll
            for (int s = 0; s < 4; s++) {
                const float rs = v[4 * s] + v[4 * s + 1] + v[4 * s + 2] + v[4 * s + 3];
                const float inv = __fdividef(1.0f, rs + 1e-6f);
                v[4 * s] *= inv; v[4 * s + 1] *= inv; v[4 * s + 2] *= inv; v[4 * s + 3] *= inv;
            }
        }
        float4* hq = reinterpret_cast<float4*>(g_hres + pix * 16);
        hq[0] = make_float4(v[0], v[1], v[2], v[3]);
        hq[1] = make_float4(v[4], v[5], v[6], v[7]);
        hq[2] = make_float4(v[8], v[9], v[10], v[11]);
        hq[3] = make_float4(v[12], v[13], v[14], v[15]);
    }
    __syncthreads();

    // ---- phase 2: x_pre DIRECT (4 threads/px, 16 ch each) ----
    {
        const int q = tid & 3;
        const int pl = tid >> 2;
        const size_t pix2 = pixbase + pl;
        const float4 hp4 = *reinterpret_cast<const float4*>(&s_hp[pl][0]);
        const float* xp2 = x + pix2 * SCn + q * 16;

        float4 xv[4][4];
#pragma unroll
        for (int s = 0; s < 4; s++)
#pragma unroll
            for (int j = 0; j < 4; j++)
                xv[s][j] = *reinterpret_cast<const float4*>(xp2 + s * 64 + j * 4);

        float v[16];
#pragma unroll
        for (int j = 0; j < 4; j++) {
            v[j * 4 + 0] = hp4.x * xv[0][j].x + hp4.y * xv[1][j].x + hp4.z * xv[2][j].x + hp4.w * xv[3][j].x;
            v[j * 4 + 1] = hp4.x * xv[0][j].y + hp4.y * xv[1][j].y + hp4.z * xv[2][j].y + hp4.w * xv[3][j].y;
            v[j * 4 + 2] = hp4.x * xv[0][j].z + hp4.y * xv[1][j].z + hp4.z * xv[2][j].z + hp4.w * xv[3][j].z;
            v[j * 4 + 3] = hp4.x * xv[0][j].w + hp4.y * xv[1][j].w + hp4.z * xv[2][j].w + hp4.w * xv[3][j].w;
        }

        uint32_t uhi[8], ulo[8];
#pragma unroll
        for (int k2 = 0; k2 < 8; k2++) {
            const float a = v[2 * k2], b2 = v[2 * k2 + 1];
            const __nv_bfloat16 ah = __float2bfloat16(a), bh = __float2bfloat16(b2);
            uhi[k2] = (uint32_t)__bfloat16_as_ushort(ah) | ((uint32_t)__bfloat16_as_ushort(bh) << 16);
            const __nv_bfloat16 al = __float2bfloat16(a - __bfloat162float(ah));
            const __nv_bfloat16 bl = __float2bfloat16(b2 - __bfloat162float(bh));
            ulo[k2] = (uint32_t)__bfloat16_as_ushort(al) | ((uint32_t)__bfloat16_as_ushort(bl) << 16);
        }
        uint4* dst = reinterpret_cast<uint4*>(g_xpb + pix2 * 128);
        dst[q * 2 + 0]     = make_uint4(uhi[0], uhi[1], uhi[2], uhi[3]);
        dst[q * 2 + 1]     = make_uint4(uhi[4], uhi[5], uhi[6], uhi[7]);
        dst[8 + q * 2 + 0] = make_uint4(ulo[0], ulo[1], ulo[2], ulo[3]);
        dst[8 + q * 2 + 1] = make_uint4(ulo[4], ulo[5], ulo[6], ulo[7]);
    }
}

// ---------------------------------------------------------------------------
// Kernel 2: conv via mma.sync bf16 (unchanged from R11)
// ---------------------------------------------------------------------------
constexpr int AROW = 272;                     // bytes per px slot (17 x 16B)
constexpr int AKY  = 66 * AROW;               // 17952 per raw input row
constexpr int A_RAW = 3 * AKY;                // 53856
constexpr int BROW = 144;                     // B chunk row stride (9 x 16B)
constexpr int BBUF1 = 64 * BROW;              // 9216
constexpr int CONV_SMEM = A_RAW + 2 * BBUF1;  // 72288
constexpr int SLS = 68;                       // layer_out stage stride

__device__ __forceinline__ void issue_b_chunk(uint32_t sb, int c, int tid)
{
    const int ky = c / 6, sub = c - ky * 6;
    const int var = (sub >= 3) ? 1 : 0;
    const int kx = var ? sub - 3 : sub;
    const uint32_t dst = sb + (uint32_t)((c & 1) * BBUF1);
    const __nv_bfloat16* src = g_wb + (size_t)(ky * 2 + var) * 12288 + kx * 64;
#pragma unroll
    for (int i = 0; i < 2; i++) {
        const int e = tid + i * 256;
        const int row = e >> 3, q = e & 7;
        cp16(dst + row * BROW + q * 16, src + row * 192 + q * 8);
    }
}

__global__ void __launch_bounds__(256, 3) conv_kernel(const float* __restrict__ x,
                                                      float* __restrict__ out)
{
    extern __shared__ __align__(16) char smem[];
    char* s_a = smem;
    const uint32_t sa = smem_u32(smem);
    const uint32_t sb = sa + A_RAW;

    const int tid = threadIdx.x;
    const int wid = tid >> 5, lane = tid & 31;
    const int ks = wid & 1;
    const int wm = (wid >> 1) & 1;
    const int wn = wid >> 2;
    const int xh = blockIdx.x;
    const int y = blockIdx.y, b = blockIdx.z;

    {
        const uint4 z = make_uint4(0, 0, 0, 0);
#pragma unroll 1
        for (int e = tid; e < 3 * 66 * 16; e += 256) {
            const int ky = e / 1056, rem = e - ky * 1056;
            const int p = rem >> 4, q = rem & 15;
            const int y2 = y + ky - 1;
            const int gx = xh * 64 + p - 1;
            const uint32_t dst = sa + (uint32_t)(ky * AKY + p * AROW + q * 16);
            if ((unsigned)y2 < 128u && (unsigned)gx < 128u)
                cp16(dst, g_xpb + (((size_t)(b * 128 + y2) * 128 + gx) * 128) + q * 8);
            else
                *reinterpret_cast<uint4*>(s_a + (ky * AKY + p * AROW + q * 16)) = z;
        }
    }
    issue_b_chunk(sb, 0, tid);
    CP_COMMIT();
    issue_b_chunk(sb, 1, tid);
    CP_COMMIT();

    float d[2][4][4];
#pragma unroll
    for (int mt = 0; mt < 2; mt++)
#pragma unroll
        for (int t = 0; t < 4; t++)
#pragma unroll
            for (int j = 0; j < 4; j++) d[mt][t][j] = 0.f;

    const uint32_t a_lane = sa + (uint32_t)((32 * wm + (lane & 15)) * AROW)
                               + (uint32_t)((lane >> 4) << 4);
    uint32_t b_lane[2];
#pragma unroll
    for (int t = 0; t < 2; t++)
        b_lane[t] = sb + (uint32_t)((32 * wn + 16 * t + (lane & 7) + ((lane >> 4) << 3)) * BROW)
                       + (uint32_t)(((lane >> 3) & 1) << 4);

#pragma unroll 1
    for (int c = 0; c < 18; c++) {
        if (c < 17) { CP_WAIT1(); } else { CP_WAIT0(); }
        __syncthreads();

        const int ky = c / 6, sub = c - ky * 6;
        const int var = (sub >= 3) ? 1 : 0;
        const int kx = var ? sub - 3 : sub;
        const uint32_t a_base = a_lane + (uint32_t)(ky * AKY + kx * AROW);
        const uint32_t b_base = (uint32_t)((c & 1) * BBUF1);

        if (!var) {
            const uint32_t ap = a_base + (uint32_t)(ks * 128);
#pragma unroll
            for (int j2 = 0; j2 < 4; j2++) {
                uint32_t a0[4], a1[4];
                ldsm4(a0[0], a0[1], a0[2], a0[3], ap + j2 * 32);
                ldsm4(a1[0], a1[1], a1[2], a1[3], ap + 16 * AROW + j2 * 32);
#pragma unroll
                for (int t = 0; t < 2; t++) {
                    uint32_t b0, b1, b2, b3;
                    ldsm4(b0, b1, b2, b3, b_lane[t] + b_base + j2 * 32);
                    mma16816(d[0][2 * t],     a0[0], a0[1], a0[2], a0[3], b0, b1);
                    mma16816(d[0][2 * t + 1], a0[0], a0[1], a0[2], a0[3], b2, b3);
                    mma16816(d[1][2 * t],     a1[0], a1[1], a1[2], a1[3], b0, b1);
                    mma16816(d[1][2 * t + 1], a1[0], a1[1], a1[2], a1[3], b2, b3);
                }
            }
        } else {
#pragma unroll
            for (int jj = 0; jj < 2; jj++) {
                const int j2 = 2 * ks + jj;
                uint32_t a0[4], a1[4];
                ldsm4(a0[0], a0[1], a0[2], a0[3], a_base + j2 * 32);
                ldsm4(a1[0], a1[1], a1[2], a1[3], a_base + 16 * AROW + j2 * 32);
#pragma unroll
                for (int t = 0; t < 2; t++) {
                    uint32_t b0, b1, b2, b3;
                    ldsm4(b0, b1, b2, b3, b_lane[t] + b_base + j2 * 32);
                    mma16816(d[0][2 * t],     a0[0], a0[1], a0[2], a0[3], b0, b1);
                    mma16816(d[0][2 * t + 1], a0[0], a0[1], a0[2], a0[3], b2, b3);
                    mma16816(d[1][2 * t],     a1[0], a1[1], a1[2], a1[3], b0, b1);
                    mma16816(d[1][2 * t + 1], a1[0], a1[1], a1[2], a1[3], b2, b3);
                }
            }
        }

        __syncthreads();
        if (c < 16) { issue_b_chunk(sb, c + 2, tid); CP_COMMIT(); }
    }

    __syncthreads();
    float* s_l = reinterpret_cast<float*>(smem);
    {
        float* dstc = s_l + ks * (64 * SLS);
        const int gid = lane >> 2, tig = lane & 3;
#pragma unroll
        for (int mt = 0; mt < 2; mt++)
#pragma unroll
            for (int t = 0; t < 2; t++)
#pragma unroll
                for (int h = 0; h < 2; h++) {
                    const int nt = 2 * t + h;
                    const int row0 = 32 * wm + 16 * mt + gid;
                    const int col = 32 * wn + 16 * t + 8 * h + 2 * tig;
                    dstc[row0 * SLS + col]           = d[mt][nt][0];
                    dstc[row0 * SLS + col + 1]       = d[mt][nt][1];
                    dstc[(row0 + 8) * SLS + col]     = d[mt][nt][2];
                    dstc[(row0 + 8) * SLS + col + 1] = d[mt][nt][3];
                }
    }
    __syncthreads();

    const size_t rowpix = ((size_t)b * 128 + y) * 128 + xh * 64;
    const int cq = tid & 15;
#pragma unroll 1
    for (int i = 0; i < 4; ++i) {
        const int m = i * 16 + (tid >> 4);
        const size_t pix = rowpix + m;
        const float* xp = x + pix * SCn;
        const float4* hq = reinterpret_cast<const float4*>(g_hres + pix * 16);
        float4 hr[4];
        hr[0] = hq[0]; hr[1] = hq[1]; hr[2] = hq[2]; hr[3] = hq[3];
        const float4 hpst = *reinterpret_cast<const float4*>(g_hpost + pix * 4);
        const float hpo[4] = {hpst.x, hpst.y, hpst.z, hpst.w};

        float4 xv[4];
#pragma unroll
        for (int t = 0; t < 4; t++)
            xv[t] = *reinterpret_cast<const float4*>(xp + t * 64 + cq * 4);

        const float4 l0 = *reinterpret_cast<const float4*>(s_l + m * SLS + cq * 4);
        const float4 l1 = *reinterpret_cast<const float4*>(s_l + 64 * SLS + m * SLS + cq * 4);
        const float lx = l0.x + l1.x, ly = l0.y + l1.y, lz = l0.z + l1.z, lw = l0.w + l1.w;

        float* op = out + pix * SCn;
#pragma unroll
        for (int o = 0; o < 4; o++) {
            float4 r;
            r.x = hr[o].x * xv[0].x + hr[o].y * xv[1].x + hr[o].z * xv[2].x + hr[o].w * xv[3].x + hpo[o] * lx;
            r.y = hr[o].x * xv[0].y + hr[o].y * xv[1].y + hr[o].z * xv[2].y + hr[o].w * xv[3].y + hpo[o] * ly;
            r.z = hr[o].x * xv[0].z + hr[o].y * xv[1].z + hr[o].z * xv[2].z + hr[o].w * xv[3].z + hpo[o] * lz;
            r.w = hr[o].x * xv[0].w + hr[o].y * xv[1].w + hr[o].z * xv[2].w + hr[o].w * xv[3].w + hpo[o] * lw;
            *reinterpret_cast<float4*>(op + o * 64 + cq * 4) = r;
        }
    }
}

// ---------------------------------------------------------------------------
extern "C" void kernel_launch(void* const* d_in, const int* in_sizes, int n_in,
                              void* d_out, int out_size)
{
    const float* x       = (const float*)d_in[0];
    const float* w_pre   = (const float*)d_in[1];
    const float* w_post  = (const float*)d_in[2];
    const float* w_res   = (const float*)d_in[3];
    const float* b_pre   = (const float*)d_in[4];
    const float* b_res   = (const float*)d_in[5];
    const float* b_post  = (const float*)d_in[6];
    const float* a_pre   = (const float*)d_in[7];
    const float* a_res   = (const float*)d_in[8];
    const float* a_post  = (const float*)d_in[9];
    const float* rms_w   = (const float*)d_in[10];
    const float* conv_w  = (const float*)d_in[11];
    float* out = (float*)d_out;

    wprep_kernel<<<(6 * 64 * 192 + 255) / 256, 256>>>(conv_w);
    wprep2_kernel<<<(2 * 32 * 256 + 255) / 256, 256>>>(w_pre, w_post, w_res,
                                                       a_pre, a_res, a_post, rms_w);

    cudaFuncSetAttribute(proj_kernel, cudaFuncAttributeMaxDynamicSharedMemorySize, PROJ_SMEM);
    proj_kernel<<<NPIX / 64, 256, PROJ_SMEM>>>(x, b_pre, b_res, b_post);

    cudaFuncSetAttribute(conv_kernel, cudaFuncAttributeMaxDynamicSharedMemorySize, CONV_SMEM);
    conv_kernel<<<dim3(2, Hn, Bn), 256, CONV_SMEM>>>(x, out);
}

// round 13
// speedup vs baseline: 1.6316x; 1.6316x over previous
#include <cuda_runtime.h>
#include <cuda_bf16.h>
#include <cstdint>

#define FULL 0xffffffffu

constexpr int Bn = 16, Hn = 128, Wn = 128, Sn = 4, Cn = 64;
constexpr int SCn = Sn * Cn;                // 256
constexpr int NPIX = Bn * Hn * Wn;          // 262144

// Scratch (static device arrays -- allocation-free rule)
__device__ __nv_bfloat16 g_xpb[(size_t)NPIX * 128];        // [pix][hi(64)|lo(64)] bf16
__device__ __align__(16) float g_hpost[(size_t)NPIX * Sn]; // [pix][4]
__device__ __align__(16) float g_hres[(size_t)NPIX * 16];  // [pix][16] (sinkhorn'd)
__device__ __nv_bfloat16 g_wb[6 * 64 * 192];               // conv W: [ky*2+var][co][k=(kx,ci)=192]

union F2U { float2 f; unsigned long long u; };

__device__ __forceinline__ unsigned long long pack2(float v) {
    F2U t; t.f = make_float2(v, v); return t.u;
}
__device__ __forceinline__ void ffma2(unsigned long long& d, unsigned long long a, unsigned long long b) {
    asm("fma.rn.f32x2 %0, %1, %2, %0;" : "+l"(d) : "l"(a), "l"(b));
}
__device__ __forceinline__ uint32_t smem_u32(const void* p) {
    uint32_t a;
    asm("{ .reg .u64 t; cvta.to.shared.u64 t, %1; cvt.u32.u64 %0, t; }" : "=r"(a) : "l"(p));
    return a;
}
__device__ __forceinline__ void ldsm4(uint32_t& r0, uint32_t& r1, uint32_t& r2, uint32_t& r3, uint32_t addr) {
    asm volatile("ldmatrix.sync.aligned.m8n8.x4.shared.b16 {%0,%1,%2,%3}, [%4];"
                 : "=r"(r0), "=r"(r1), "=r"(r2), "=r"(r3) : "r"(addr));
}
__device__ __forceinline__ void mma16816(float* d, uint32_t a0, uint32_t a1, uint32_t a2, uint32_t a3,
                                         uint32_t b0, uint32_t b1) {
    asm volatile("mma.sync.aligned.m16n8k16.row.col.f32.bf16.bf16.f32 "
                 "{%0,%1,%2,%3}, {%4,%5,%6,%7}, {%8,%9}, {%0,%1,%2,%3};"
                 : "+f"(d[0]), "+f"(d[1]), "+f"(d[2]), "+f"(d[3])
                 : "r"(a0), "r"(a1), "r"(a2), "r"(a3), "r"(b0), "r"(b1));
}
__device__ __forceinline__ void cp16(uint32_t smaddr, const void* g) {
    asm volatile("cp.async.cg.shared.global [%0], [%1], 16;" :: "r"(smaddr), "l"(g));
}
#define CP_COMMIT() asm volatile("cp.async.commit_group;" ::: "memory")
#define CP_WAIT0()  asm volatile("cp.async.wait_group 0;" ::: "memory")
#define CP_WAIT1()  asm volatile("cp.async.wait_group 1;" ::: "memory")

// ---------------------------------------------------------------------------
// Kernel 0: conv weight prep (unchanged)
// ---------------------------------------------------------------------------
__global__ void wprep_kernel(const float* __restrict__ conv_w)
{
    const int e = blockIdx.x * 256 + threadIdx.x;
    if (e >= 6 * 64 * 192) return;
    const int tile = e / (64 * 192);
    const int rem = e - tile * (64 * 192);
    const int co = rem / 192, k = rem - co * 192;
    const int ky = tile >> 1, var = tile & 1;
    const int kx = k >> 6, ci = k & 63;
    const float w = conv_w[((size_t)(ky * 3 + kx) * 64 + ci) * 64 + co];
    const __nv_bfloat16 hi = __float2bfloat16(w);
    __nv_bfloat16 v = hi;
    if (var) v = __float2bfloat16(w - __bfloat162float(hi));
    g_wb[e] = v;
}

// ---------------------------------------------------------------------------
// Kernel 1: projections + Sinkhorn + x_pre (EXACT R11 version — known good)
// ---------------------------------------------------------------------------
constexpr int SX_STRIDE = 33;
constexpr int SX_FLOATS = 256 * SX_STRIDE;              // 8448
constexpr int SW_FLOATS = 256 * 24;                     // 6144
constexpr int PROJ_SMEM = (SX_FLOATS + SW_FLOATS) * 4;  // 58368 B

__global__ void __launch_bounds__(256) proj_kernel(
    const float* __restrict__ x,
    const float* __restrict__ w_pre, const float* __restrict__ w_post, const float* __restrict__ w_res,
    const float* __restrict__ b_pre, const float* __restrict__ b_res, const float* __restrict__ b_post,
    const float* __restrict__ alpha_pre, const float* __restrict__ alpha_res, const float* __restrict__ alpha_post,
    const float* __restrict__ rms_w)
{
    extern __shared__ __align__(16) float dsm[];
    float* s_x = dsm;                    // phase1: [256][SX_STRIDE]
    float* s_w = dsm + SX_FLOATS;        // phase1: [256 features][24 outputs]
    __shared__ float b_all[24];
    __shared__ __align__(16) float s_hp[256][4];

    const int tid = threadIdx.x;
    {
        const int f = tid;
        const float rw = rms_w[f];
        const float apre = alpha_pre[0], ares = alpha_res[0], apost = alpha_post[0];
#pragma unroll
        for (int o = 0; o < 4; o++)  s_w[f * 24 + o]      = apre  * w_pre[o * SCn + f]  * rw;
#pragma unroll
        for (int o = 0; o < 16; o++) s_w[f * 24 + 4 + o]  = ares  * w_res[o * SCn + f]  * rw;
#pragma unroll
        for (int o = 0; o < 4; o++)  s_w[f * 24 + 20 + o] = apost * w_post[o * SCn + f] * rw;
        if (tid < 4)       b_all[tid] = b_pre[tid];
        else if (tid < 20) b_all[tid] = b_res[tid - 4];
        else if (tid < 24) b_all[tid] = b_post[tid - 20];
    }

    const size_t pixbase = (size_t)blockIdx.x * 256;
    const size_t pix = pixbase + tid;
    const float* xb = x + pixbase * SCn;

    unsigned long long acc[12];
#pragma unroll
    for (int j = 0; j < 12; j++) acc[j] = 0ull;
    float ss = 0.f;

    float4 rr[8];
#pragma unroll
    for (int k = 0; k < 8; k++) {
        const int e4 = tid + k * 256;
        const int p = e4 >> 3, f4 = (e4 & 7) * 4;
        rr[k] = *reinterpret_cast<const float4*>(&xb[p * SCn + 0 * 32 + f4]);
    }

#pragma unroll 1
    for (int ch = 0; ch < 8; ch++) {
        __syncthreads();
#pragma unroll
        for (int k = 0; k < 8; k++) {
            const int e4 = tid + k * 256;
            const int p = e4 >> 3, f4 = (e4 & 7) * 4;
            s_x[p * SX_STRIDE + f4 + 0] = rr[k].x;
            s_x[p * SX_STRIDE + f4 + 1] = rr[k].y;
            s_x[p * SX_STRIDE + f4 + 2] = rr[k].z;
            s_x[p * SX_STRIDE + f4 + 3] = rr[k].w;
        }
        __syncthreads();
        if (ch < 7) {
#pragma unroll
            for (int k = 0; k < 8; k++) {
                const int e4 = tid + k * 256;
                const int p = e4 >> 3, f4 = (e4 & 7) * 4;
                rr[k] = *reinterpret_cast<const float4*>(&xb[p * SCn + (ch + 1) * 32 + f4]);
            }
        }
#pragma unroll
        for (int f = 0; f < 32; f++) {
            const float xf = s_x[tid * SX_STRIDE + f];
            ss = fmaf(xf, xf, ss);
            const unsigned long long xx = pack2(xf);
            const ulonglong2* w2 = reinterpret_cast<const ulonglong2*>(s_w + (ch * 32 + f) * 24);
#pragma unroll
            for (int q = 0; q < 6; q++) {
                const ulonglong2 w = w2[q];
                ffma2(acc[2 * q],     xx, w.x);
                ffma2(acc[2 * q + 1], xx, w.y);
            }
        }
    }

    const float rms = rsqrtf(ss * (1.0f / 256.0f) + 1.1920929e-07f);
    float s24[24];
#pragma unroll
    for (int j = 0; j < 12; j++) {
        F2U t; t.u = acc[j];
        s24[2 * j] = t.f.x; s24[2 * j + 1] = t.f.y;
    }

#pragma unroll
    for (int s = 0; s < 4; s++)
        s_hp[tid][s] = __fdividef(1.0f, 1.0f + __expf(-(s24[s] * rms + b_all[s])));
    {
        float4 hq;
        hq.x = __fdividef(2.0f, 1.0f + __expf(-(s24[20] * rms + b_all[20])));
        hq.y = __fdividef(2.0f, 1.0f + __expf(-(s24[21] * rms + b_all[21])));
        hq.z = __fdividef(2.0f, 1.0f + __expf(-(s24[22] * rms + b_all[22])));
        hq.w = __fdividef(2.0f, 1.0f + __expf(-(s24[23] * rms + b_all[23])));
        *reinterpret_cast<float4*>(g_hpost + pix * 4) = hq;
    }

    {
        float v[16];
#pragma unroll
        for (int j = 0; j < 16; j++) v[j] = s24[4 + j] * rms + b_all[4 + j];
        float m = v[0];
#pragma unroll
        for (int j = 1; j < 16; j++) m = fmaxf(m, v[j]);
#pragma unroll
        for (int j = 0; j < 16; j++) v[j] = __expf(v[j] - m);
#pragma unroll 1
        for (int it = 0; it < 20; ++it) {
#pragma unroll
            for (int t = 0; t < 4; t++) {
                const float cs = v[t] + v[4 + t] + v[8 + t] + v[12 + t];
                const float inv = __fdividef(1.0f, cs + 1e-6f);
                v[t] *= inv; v[4 + t] *= inv; v[8 + t] *= inv; v[12 + t] *= inv;
            }
#pragma unroll
            for (int s = 0; s < 4; s++) {
                const float rs = v[4 * s] + v[4 * s + 1] + v[4 * s + 2] + v[4 * s + 3];
                const float inv = __fdividef(1.0f, rs + 1e-6f);
                v[4 * s] *= inv; v[4 * s + 1] *= inv; v[4 * s + 2] *= inv; v[4 * s + 3] *= inv;
            }
        }
        float4* hq = reinterpret_cast<float4*>(g_hres + pix * 16);
        hq[0] = make_float4(v[0], v[1], v[2], v[3]);
        hq[1] = make_float4(v[4], v[5], v[6], v[7]);
        hq[2] = make_float4(v[8], v[9], v[10], v[11]);
        hq[3] = make_float4(v[12], v[13], v[14], v[15]);
    }

    // ---------------- phase 2: x_pre DIRECT (4 threads/px, 16 ch each) ------
    __syncthreads();
    const int q = tid & 3;
#pragma unroll 1
    for (int g = 0; g < 4; g++) {
        const int pl = g * 64 + (tid >> 2);
        const size_t pix2 = pixbase + pl;
        const float4 hp4 = *reinterpret_cast<const float4*>(&s_hp[pl][0]);
        const float* xp2 = x + pix2 * SCn + q * 16;

        float4 xv[4][4];
#pragma unroll
        for (int s = 0; s < 4; s++)
#pragma unroll
            for (int j = 0; j < 4; j++)
                xv[s][j] = *reinterpret_cast<const float4*>(xp2 + s * 64 + j * 4);

        float v[16];
#pragma unroll
        for (int j = 0; j < 4; j++) {
            v[j * 4 + 0] = hp4.x * xv[0][j].x + hp4.y * xv[1][j].x + hp4.z * xv[2][j].x + hp4.w * xv[3][j].x;
            v[j * 4 + 1] = hp4.x * xv[0][j].y + hp4.y * xv[1][j].y + hp4.z * xv[2][j].y + hp4.w * xv[3][j].y;
            v[j * 4 + 2] = hp4.x * xv[0][j].z + hp4.y * xv[1][j].z + hp4.z * xv[2][j].z + hp4.w * xv[3][j].z;
            v[j * 4 + 3] = hp4.x * xv[0][j].w + hp4.y * xv[1][j].w + hp4.z * xv[2][j].w + hp4.w * xv[3][j].w;
        }

        uint32_t uhi[8], ulo[8];
#pragma unroll
        for (int k2 = 0; k2 < 8; k2++) {
            const float a = v[2 * k2], b2 = v[2 * k2 + 1];
            const __nv_bfloat16 ah = __float2bfloat16(a), bh = __float2bfloat16(b2);
            uhi[k2] = (uint32_t)__bfloat16_as_ushort(ah) | ((uint32_t)__bfloat16_as_ushort(bh) << 16);
            const __nv_bfloat16 al = __float2bfloat16(a - __bfloat162float(ah));
            const __nv_bfloat16 bl = __float2bfloat16(b2 - __bfloat162float(bh));
            ulo[k2] = (uint32_t)__bfloat16_as_ushort(al) | ((uint32_t)__bfloat16_as_ushort(bl) << 16);
        }
        uint4* dst = reinterpret_cast<uint4*>(g_xpb + pix2 * 128);
        dst[q * 2 + 0]     = make_uint4(uhi[0], uhi[1], uhi[2], uhi[3]);
        dst[q * 2 + 1]     = make_uint4(uhi[4], uhi[5], uhi[6], uhi[7]);
        dst[8 + q * 2 + 0] = make_uint4(ulo[0], ulo[1], ulo[2], ulo[3]);
        dst[8 + q * 2 + 1] = make_uint4(ulo[4], ulo[5], ulo[6], ulo[7]);
    }
}

// ---------------------------------------------------------------------------
// Kernel 2: conv via mma.sync bf16. NEW warp tiling: 8 warps = 2M(32) x 4Ksplit,
// each warp owns ALL of N (n64) and one k16 slice (j2 = ks) -> B loaded once,
// reused for both A parts (hi chunks): 8 ldsm : 32 mma. 2-slot B ring.
// 4-way K-split merged in two s_l rounds.
// ---------------------------------------------------------------------------
constexpr int AROW = 272;                     // bytes per px slot (17 x 16B)
constexpr int AKY  = 66 * AROW;               // 17952 per raw input row
constexpr int A_RAW = 3 * AKY;                // 53856
constexpr int BROW = 144;                     // B chunk row stride (9 x 16B)
constexpr int BBUF1 = 64 * BROW;              // 9216
constexpr int CONV_SMEM = A_RAW + 2 * BBUF1;  // 72288
constexpr int SLS = 68;                       // layer_out stage stride

__device__ __forceinline__ void issue_b_chunk(uint32_t sb, int c, int tid)
{
    const int ky = c / 6, sub = c - ky * 6;
    const int var = (sub >= 3) ? 1 : 0;
    const int kx = var ? sub - 3 : sub;
    const uint32_t dst = sb + (uint32_t)((c & 1) * BBUF1);
    const __nv_bfloat16* src = g_wb + (size_t)(ky * 2 + var) * 12288 + kx * 64;
#pragma unroll
    for (int i = 0; i < 2; i++) {
        const int e = tid + i * 256;
        const int row = e >> 3, q = e & 7;
        cp16(dst + row * BROW + q * 16, src + row * 192 + q * 8);
    }
}

__global__ void __launch_bounds__(256, 2) conv_kernel(const float* __restrict__ x,
                                                      float* __restrict__ out)
{
    extern __shared__ __align__(16) char smem[];
    char* s_a = smem;
    const uint32_t sa = smem_u32(smem);
    const uint32_t sb = sa + A_RAW;

    const int tid = threadIdx.x;
    const int wid = tid >> 5, lane = tid & 31;
    const int wm = wid & 1;                      // m32 half
    const int ks = wid >> 1;                     // k16 slice (j2) 0..3
    const int xh = blockIdx.x;
    const int y = blockIdx.y, b = blockIdx.z;

    // ---- prologue: A (3 raw rows, halo slots) + B chunks 0,1 ----
    {
        const uint4 z = make_uint4(0, 0, 0, 0);
#pragma unroll 1
        for (int e = tid; e < 3 * 66 * 16; e += 256) {
            const int ky = e / 1056, rem = e - ky * 1056;
            const int p = rem >> 4, q = rem & 15;
            const int y2 = y + ky - 1;
            const int gx = xh * 64 + p - 1;
            const uint32_t dst = sa + (uint32_t)(ky * AKY + p * AROW + q * 16);
            if ((unsigned)y2 < 128u && (unsigned)gx < 128u)
                cp16(dst, g_xpb + (((size_t)(b * 128 + y2) * 128 + gx) * 128) + q * 8);
            else
                *reinterpret_cast<uint4*>(s_a + (ky * AKY + p * AROW + q * 16)) = z;
        }
    }
    issue_b_chunk(sb, 0, tid);
    CP_COMMIT();
    issue_b_chunk(sb, 1, tid);
    CP_COMMIT();

    float d[2][8][4];   // [m16 tile][n8 tile][frag]
#pragma unroll
    for (int mt = 0; mt < 2; mt++)
#pragma unroll
        for (int t = 0; t < 8; t++)
#pragma unroll
            for (int j = 0; j < 4; j++) d[mt][t][j] = 0.f;

    const uint32_t a_lane = sa + (uint32_t)((32 * wm + (lane & 15)) * AROW)
                               + (uint32_t)((lane >> 4) << 4);
    uint32_t b_lane[4];
#pragma unroll
    for (int t = 0; t < 4; t++)
        b_lane[t] = sb + (uint32_t)((16 * t + (lane & 7) + ((lane >> 4) << 3)) * BROW)
                       + (uint32_t)(((lane >> 3) & 1) << 4);

#pragma unroll 1
    for (int c = 0; c < 18; c++) {
        if (c < 17) { CP_WAIT1(); } else { CP_WAIT0(); }
        __syncthreads();

        const int ky = c / 6, sub = c - ky * 6;
        const int var = (sub >= 3) ? 1 : 0;
        const int kx = var ? sub - 3 : sub;
        const uint32_t a_base = a_lane + (uint32_t)(ky * AKY + kx * AROW) + (uint32_t)(ks * 32);
        const uint32_t b_base = (uint32_t)((c & 1) * BBUF1) + (uint32_t)(ks * 32);

        // B fragments for this warp's k16 slice, n64 (loaded once)
        uint32_t bf[4][4];
#pragma unroll
        for (int t = 0; t < 4; t++)
            ldsm4(bf[t][0], bf[t][1], bf[t][2], bf[t][3], b_lane[t] + b_base);

        // A part hi (offset 0)
        {
            uint32_t a0[4], a1[4];
            ldsm4(a0[0], a0[1], a0[2], a0[3], a_base);
            ldsm4(a1[0], a1[1], a1[2], a1[3], a_base + 16 * AROW);
#pragma unroll
            for (int t = 0; t < 4; t++) {
                mma16816(d[0][2 * t],     a0[0], a0[1], a0[2], a0[3], bf[t][0], bf[t][1]);
                mma16816(d[0][2 * t + 1], a0[0], a0[1], a0[2], a0[3], bf[t][2], bf[t][3]);
                mma16816(d[1][2 * t],     a1[0], a1[1], a1[2], a1[3], bf[t][0], bf[t][1]);
                mma16816(d[1][2 * t + 1], a1[0], a1[1], a1[2], a1[3], bf[t][2], bf[t][3]);
            }
        }
        // A part lo (offset 128) only for hi-B chunks
        if (!var) {
            uint32_t a0[4], a1[4];
            ldsm4(a0[0], a0[1], a0[2], a0[3], a_base + 128);
            ldsm4(a1[0], a1[1], a1[2], a1[3], a_base + 128 + 16 * AROW);
#pragma unroll
            for (int t = 0; t < 4; t++) {
                mma16816(d[0][2 * t],     a0[0], a0[1], a0[2], a0[3], bf[t][0], bf[t][1]);
                mma16816(d[0][2 * t + 1], a0[0], a0[1], a0[2], a0[3], bf[t][2], bf[t][3]);
                mma16816(d[1][2 * t],     a1[0], a1[1], a1[2], a1[3], bf[t][0], bf[t][1]);
                mma16816(d[1][2 * t + 1], a1[0], a1[1], a1[2], a1[3], bf[t][2], bf[t][3]);
            }
        }

        __syncthreads();   // slot (c&1) free for overwrite
        if (c < 16) { issue_b_chunk(sb, c + 2, tid); CP_COMMIT(); }
    }

    __syncthreads();
    // ---- 4-way K-split merge: round 1 writes (ks<2), round 2 adds (ks>=2) ----
    float* s_l = reinterpret_cast<float*>(smem);
    const int gid = lane >> 2, tig = lane & 3;
    if (ks < 2) {
        float* dstc = s_l + ks * (64 * SLS);
#pragma unroll
        for (int mt = 0; mt < 2; mt++)
#pragma unroll
            for (int t = 0; t < 4; t++) {
                const int row0 = 32 * wm + 16 * mt + gid;
                const int col = 16 * t + 2 * tig;
                dstc[row0 * SLS + col]           = d[mt][2 * t][0];
                dstc[row0 * SLS + col + 1]       = d[mt][2 * t][1];
                dstc[(row0 + 8) * SLS + col]     = d[mt][2 * t][2];
                dstc[(row0 + 8) * SLS + col + 1] = d[mt][2 * t][3];
                dstc[row0 * SLS + col + 8]           = d[mt][2 * t + 1][0];
                dstc[row0 * SLS + col + 8 + 1]       = d[mt][2 * t + 1][1];
                dstc[(row0 + 8) * SLS + col + 8]     = d[mt][2 * t + 1][2];
                dstc[(row0 + 8) * SLS + col + 8 + 1] = d[mt][2 * t + 1][3];
            }
    }
    __syncthreads();
    if (ks >= 2) {
        float* dstc = s_l + (ks - 2) * (64 * SLS);
#pragma unroll
        for (int mt = 0; mt < 2; mt++)
#pragma unroll
            for (int t = 0; t < 4; t++) {
                const int row0 = 32 * wm + 16 * mt + gid;
                const int col = 16 * t + 2 * tig;
                dstc[row0 * SLS + col]           += d[mt][2 * t][0];
                dstc[row0 * SLS + col + 1]       += d[mt][2 * t][1];
                dstc[(row0 + 8) * SLS + col]     += d[mt][2 * t][2];
                dstc[(row0 + 8) * SLS + col + 1] += d[mt][2 * t][3];
                dstc[row0 * SLS + col + 8]           += d[mt][2 * t + 1][0];
                dstc[row0 * SLS + col + 8 + 1]       += d[mt][2 * t + 1][1];
                dstc[(row0 + 8) * SLS + col + 8]     += d[mt][2 * t + 1][2];
                dstc[(row0 + 8) * SLS + col + 8 + 1] += d[mt][2 * t + 1][3];
            }
    }
    __syncthreads();

    // ---- epilogue (vectorized): out = einsum(h_res, x) + h_post*(l0+l1) ----
    const size_t rowpix = ((size_t)b * 128 + y) * 128 + xh * 64;
    const int cq = tid & 15;
#pragma unroll 1
    for (int i = 0; i < 4; ++i) {
        const int m = i * 16 + (tid >> 4);
        const size_t pix = rowpix + m;
        const float* xp = x + pix * SCn;
        const float4* hq = reinterpret_cast<const float4*>(g_hres + pix * 16);
        float4 hr[4];
        hr[0] = hq[0]; hr[1] = hq[1]; hr[2] = hq[2]; hr[3] = hq[3];
        const float4 hpst = *reinterpret_cast<const float4*>(g_hpost + pix * 4);
        const float hpo[4] = {hpst.x, hpst.y, hpst.z, hpst.w};

        float4 xv[4];
#pragma unroll
        for (int t = 0; t < 4; t++)
            xv[t] = *reinterpret_cast<const float4*>(xp + t * 64 + cq * 4);

        const float4 l0 = *reinterpret_cast<const float4*>(s_l + m * SLS + cq * 4);
        const float4 l1 = *reinterpret_cast<const float4*>(s_l + 64 * SLS + m * SLS + cq * 4);
        const float lx = l0.x + l1.x, ly = l0.y + l1.y, lz = l0.z + l1.z, lw = l0.w + l1.w;

        float* op = out + pix * SCn;
#pragma unroll
        for (int o = 0; o < 4; o++) {
            float4 r;
            r.x = hr[o].x * xv[0].x + hr[o].y * xv[1].x + hr[o].z * xv[2].x + hr[o].w * xv[3].x + hpo[o] * lx;
            r.y = hr[o].x * xv[0].y + hr[o].y * xv[1].y + hr[o].z * xv[2].y + hr[o].w * xv[3].y + hpo[o] * ly;
            r.z = hr[o].x * xv[0].z + hr[o].y * xv[1].z + hr[o].z * xv[2].z + hr[o].w * xv[3].z + hpo[o] * lz;
            r.w = hr[o].x * xv[0].w + hr[o].y * xv[1].w + hr[o].w * xv[3].w + hr[o].z * xv[2].w + hpo[o] * lw;
            *reinterpret_cast<float4*>(op + o * 64 + cq * 4) = r;
        }
    }
}

// ---------------------------------------------------------------------------
extern "C" void kernel_launch(void* const* d_in, const int* in_sizes, int n_in,
                              void* d_out, int out_size)
{
    const float* x       = (const float*)d_in[0];
    const float* w_pre   = (const float*)d_in[1];
    const float* w_post  = (const float*)d_in[2];
    const float* w_res   = (const float*)d_in[3];
    const float* b_pre   = (const float*)d_in[4];
    const float* b_res   = (const float*)d_in[5];
    const float* b_post  = (const float*)d_in[6];
    const float* a_pre   = (const float*)d_in[7];
    const float* a_res   = (const float*)d_in[8];
    const float* a_post  = (const float*)d_in[9];
    const float* rms_w   = (const float*)d_in[10];
    const float* conv_w  = (const float*)d_in[11];
    float* out = (float*)d_out;

    wprep_kernel<<<(6 * 64 * 192 + 255) / 256, 256>>>(conv_w);

    cudaFuncSetAttribute(proj_kernel, cudaFuncAttributeMaxDynamicSharedMemorySize, PROJ_SMEM);
    proj_kernel<<<NPIX / 256, 256, PROJ_SMEM>>>(x, w_pre, w_post, w_res,
                                                b_pre, b_res, b_post,
                                                a_pre, a_res, a_post, rms_w);

    cudaFuncSetAttribute(conv_kernel, cudaFuncAttributeMaxDynamicSharedMemorySize, CONV_SMEM);
    conv_kernel<<<dim3(2, Hn, Bn), 256, CONV_SMEM>>>(x, out);
}

// round 14
// speedup vs baseline: 1.8153x; 1.1126x over previous
#include <cuda_runtime.h>
#include <cuda_bf16.h>
#include <cstdint>

#define FULL 0xffffffffu

constexpr int Bn = 16, Hn = 128, Wn = 128, Sn = 4, Cn = 64;
constexpr int SCn = Sn * Cn;                // 256
constexpr int NPIX = Bn * Hn * Wn;          // 262144

// Scratch (static device arrays -- allocation-free rule)
__device__ __nv_bfloat16 g_xpb[(size_t)NPIX * 128];        // [pix][hi(64)|lo(64)] bf16
__device__ __align__(16) float g_hpost[(size_t)NPIX * Sn]; // [pix][4]
__device__ __align__(16) float g_hres[(size_t)NPIX * 16];  // [pix][16] (sinkhorn'd)
__device__ __nv_bfloat16 g_wb[6 * 64 * 192];               // conv W: [ky*2+var][co][k=(kx,ci)=192]

union F2U { float2 f; unsigned long long u; };

__device__ __forceinline__ unsigned long long pack2(float v) {
    F2U t; t.f = make_float2(v, v); return t.u;
}
__device__ __forceinline__ void ffma2(unsigned long long& d, unsigned long long a, unsigned long long b) {
    asm("fma.rn.f32x2 %0, %1, %2, %0;" : "+l"(d) : "l"(a), "l"(b));
}
__device__ __forceinline__ uint32_t smem_u32(const void* p) {
    uint32_t a;
    asm("{ .reg .u64 t; cvta.to.shared.u64 t, %1; cvt.u32.u64 %0, t; }" : "=r"(a) : "l"(p));
    return a;
}
__device__ __forceinline__ void ldsm4(uint32_t& r0, uint32_t& r1, uint32_t& r2, uint32_t& r3, uint32_t addr) {
    asm volatile("ldmatrix.sync.aligned.m8n8.x4.shared.b16 {%0,%1,%2,%3}, [%4];"
                 : "=r"(r0), "=r"(r1), "=r"(r2), "=r"(r3) : "r"(addr));
}
__device__ __forceinline__ void mma16816(float* d, uint32_t a0, uint32_t a1, uint32_t a2, uint32_t a3,
                                         uint32_t b0, uint32_t b1) {
    asm volatile("mma.sync.aligned.m16n8k16.row.col.f32.bf16.bf16.f32 "
                 "{%0,%1,%2,%3}, {%4,%5,%6,%7}, {%8,%9}, {%0,%1,%2,%3};"
                 : "+f"(d[0]), "+f"(d[1]), "+f"(d[2]), "+f"(d[3])
                 : "r"(a0), "r"(a1), "r"(a2), "r"(a3), "r"(b0), "r"(b1));
}
__device__ __forceinline__ void cp16(uint32_t smaddr, const void* g) {
    asm volatile("cp.async.cg.shared.global [%0], [%1], 16;" :: "r"(smaddr), "l"(g));
}
#define CP_COMMIT() asm volatile("cp.async.commit_group;" ::: "memory")
#define CP_WAIT0()  asm volatile("cp.async.wait_group 0;" ::: "memory")
#define CP_WAIT1()  asm volatile("cp.async.wait_group 1;" ::: "memory")

// ---------------------------------------------------------------------------
// Kernel 1: projections + Sinkhorn + x_pre (R11 version) + conv-weight prep
// folded into the first 288 blocks (independent elementwise work).
// ---------------------------------------------------------------------------
constexpr int SX_STRIDE = 33;
constexpr int SX_FLOATS = 256 * SX_STRIDE;              // 8448
constexpr int SW_FLOATS = 256 * 24;                     // 6144
constexpr int PROJ_SMEM = (SX_FLOATS + SW_FLOATS) * 4;  // 58368 B

__global__ void __launch_bounds__(256) proj_kernel(
    const float* __restrict__ x,
    const float* __restrict__ w_pre, const float* __restrict__ w_post, const float* __restrict__ w_res,
    const float* __restrict__ b_pre, const float* __restrict__ b_res, const float* __restrict__ b_post,
    const float* __restrict__ alpha_pre, const float* __restrict__ alpha_res, const float* __restrict__ alpha_post,
    const float* __restrict__ rms_w, const float* __restrict__ conv_w)
{
    extern __shared__ __align__(16) float dsm[];
    float* s_x = dsm;                    // phase1: [256][SX_STRIDE]
    float* s_w = dsm + SX_FLOATS;        // phase1: [256 features][24 outputs]
    __shared__ float b_all[24];
    __shared__ __align__(16) float s_hp[256][4];

    const int tid = threadIdx.x;

    // folded conv weight prep (blocks 0..287 cover 6*64*192 elements exactly)
    if (blockIdx.x < 288) {
        const int e = blockIdx.x * 256 + tid;
        const int tile = e / (64 * 192);
        const int rem = e - tile * (64 * 192);
        const int co = rem / 192, k = rem - co * 192;
        const int ky = tile >> 1, var = tile & 1;
        const int kx = k >> 6, ci = k & 63;
        const float w = conv_w[((size_t)(ky * 3 + kx) * 64 + ci) * 64 + co];
        const __nv_bfloat16 hi = __float2bfloat16(w);
        __nv_bfloat16 v = hi;
        if (var) v = __float2bfloat16(w - __bfloat162float(hi));
        g_wb[e] = v;
    }

    {
        const int f = tid;
        const float rw = rms_w[f];
        const float apre = alpha_pre[0], ares = alpha_res[0], apost = alpha_post[0];
#pragma unroll
        for (int o = 0; o < 4; o++)  s_w[f * 24 + o]      = apre  * w_pre[o * SCn + f]  * rw;
#pragma unroll
        for (int o = 0; o < 16; o++) s_w[f * 24 + 4 + o]  = ares  * w_res[o * SCn + f]  * rw;
#pragma unroll
        for (int o = 0; o < 4; o++)  s_w[f * 24 + 20 + o] = apost * w_post[o * SCn + f] * rw;
        if (tid < 4)       b_all[tid] = b_pre[tid];
        else if (tid < 20) b_all[tid] = b_res[tid - 4];
        else if (tid < 24) b_all[tid] = b_post[tid - 20];
    }

    const size_t pixbase = (size_t)blockIdx.x * 256;
    const size_t pix = pixbase + tid;
    const float* xb = x + pixbase * SCn;

    unsigned long long acc[12];
#pragma unroll
    for (int j = 0; j < 12; j++) acc[j] = 0ull;
    float ss = 0.f;

    float4 rr[8];
#pragma unroll
    for (int k = 0; k < 8; k++) {
        const int e4 = tid + k * 256;
        const int p = e4 >> 3, f4 = (e4 & 7) * 4;
        rr[k] = *reinterpret_cast<const float4*>(&xb[p * SCn + 0 * 32 + f4]);
    }

#pragma unroll 1
    for (int ch = 0; ch < 8; ch++) {
        __syncthreads();
#pragma unroll
        for (int k = 0; k < 8; k++) {
            const int e4 = tid + k * 256;
            const int p = e4 >> 3, f4 = (e4 & 7) * 4;
            s_x[p * SX_STRIDE + f4 + 0] = rr[k].x;
            s_x[p * SX_STRIDE + f4 + 1] = rr[k].y;
            s_x[p * SX_STRIDE + f4 + 2] = rr[k].z;
            s_x[p * SX_STRIDE + f4 + 3] = rr[k].w;
        }
        __syncthreads();
        if (ch < 7) {
#pragma unroll
            for (int k = 0; k < 8; k++) {
                const int e4 = tid + k * 256;
                const int p = e4 >> 3, f4 = (e4 & 7) * 4;
                rr[k] = *reinterpret_cast<const float4*>(&xb[p * SCn + (ch + 1) * 32 + f4]);
            }
        }
#pragma unroll
        for (int f = 0; f < 32; f++) {
            const float xf = s_x[tid * SX_STRIDE + f];
            ss = fmaf(xf, xf, ss);
            const unsigned long long xx = pack2(xf);
            const ulonglong2* w2 = reinterpret_cast<const ulonglong2*>(s_w + (ch * 32 + f) * 24);
#pragma unroll
            for (int q = 0; q < 6; q++) {
                const ulonglong2 w = w2[q];
                ffma2(acc[2 * q],     xx, w.x);
                ffma2(acc[2 * q + 1], xx, w.y);
            }
        }
    }

    const float rms = rsqrtf(ss * (1.0f / 256.0f) + 1.1920929e-07f);
    float s24[24];
#pragma unroll
    for (int j = 0; j < 12; j++) {
        F2U t; t.u = acc[j];
        s24[2 * j] = t.f.x; s24[2 * j + 1] = t.f.y;
    }

#pragma unroll
    for (int s = 0; s < 4; s++)
        s_hp[tid][s] = __fdividef(1.0f, 1.0f + __expf(-(s24[s] * rms + b_all[s])));
    {
        float4 hq;
        hq.x = __fdividef(2.0f, 1.0f + __expf(-(s24[20] * rms + b_all[20])));
        hq.y = __fdividef(2.0f, 1.0f + __expf(-(s24[21] * rms + b_all[21])));
        hq.z = __fdividef(2.0f, 1.0f + __expf(-(s24[22] * rms + b_all[22])));
        hq.w = __fdividef(2.0f, 1.0f + __expf(-(s24[23] * rms + b_all[23])));
        *reinterpret_cast<float4*>(g_hpost + pix * 4) = hq;
    }

    {
        float v[16];
#pragma unroll
        for (int j = 0; j < 16; j++) v[j] = s24[4 + j] * rms + b_all[4 + j];
        float m = v[0];
#pragma unroll
        for (int j = 1; j < 16; j++) m = fmaxf(m, v[j]);
#pragma unroll
        for (int j = 0; j < 16; j++) v[j] = __expf(v[j] - m);
#pragma unroll 1
        for (int it = 0; it < 20; ++it) {
#pragma unroll
            for (int t = 0; t < 4; t++) {
                const float cs = v[t] + v[4 + t] + v[8 + t] + v[12 + t];
                const float inv = __fdividef(1.0f, cs + 1e-6f);
                v[t] *= inv; v[4 + t] *= inv; v[8 + t] *= inv; v[12 + t] *= inv;
            }
#pragma unroll
            for (int s = 0; s < 4; s++) {
                const float rs = v[4 * s] + v[4 * s + 1] + v[4 * s + 2] + v[4 * s + 3];
                const float inv = __fdividef(1.0f, rs + 1e-6f);
                v[4 * s] *= inv; v[4 * s + 1] *= inv; v[4 * s + 2] *= inv; v[4 * s + 3] *= inv;
            }
        }
        float4* hq = reinterpret_cast<float4*>(g_hres + pix * 16);
        hq[0] = make_float4(v[0], v[1], v[2], v[3]);
        hq[1] = make_float4(v[4], v[5], v[6], v[7]);
        hq[2] = make_float4(v[8], v[9], v[10], v[11]);
        hq[3] = make_float4(v[12], v[13], v[14], v[15]);
    }

    // ---------------- phase 2: x_pre DIRECT (4 threads/px, 16 ch each) ------
    __syncthreads();
    const int q = tid & 3;
#pragma unroll 1
    for (int g = 0; g < 4; g++) {
        const int pl = g * 64 + (tid >> 2);
        const size_t pix2 = pixbase + pl;
        const float4 hp4 = *reinterpret_cast<const float4*>(&s_hp[pl][0]);
        const float* xp2 = x + pix2 * SCn + q * 16;

        float4 xv[4][4];
#pragma unroll
        for (int s = 0; s < 4; s++)
#pragma unroll
            for (int j = 0; j < 4; j++)
                xv[s][j] = *reinterpret_cast<const float4*>(xp2 + s * 64 + j * 4);

        float v[16];
#pragma unroll
        for (int j = 0; j < 4; j++) {
            v[j * 4 + 0] = hp4.x * xv[0][j].x + hp4.y * xv[1][j].x + hp4.z * xv[2][j].x + hp4.w * xv[3][j].x;
            v[j * 4 + 1] = hp4.x * xv[0][j].y + hp4.y * xv[1][j].y + hp4.z * xv[2][j].y + hp4.w * xv[3][j].y;
            v[j * 4 + 2] = hp4.x * xv[0][j].z + hp4.y * xv[1][j].z + hp4.z * xv[2][j].z + hp4.w * xv[3][j].z;
            v[j * 4 + 3] = hp4.x * xv[0][j].w + hp4.y * xv[1][j].w + hp4.z * xv[2][j].w + hp4.w * xv[3][j].w;
        }

        uint32_t uhi[8], ulo[8];
#pragma unroll
        for (int k2 = 0; k2 < 8; k2++) {
            const float a = v[2 * k2], b2 = v[2 * k2 + 1];
            const __nv_bfloat16 ah = __float2bfloat16(a), bh = __float2bfloat16(b2);
            uhi[k2] = (uint32_t)__bfloat16_as_ushort(ah) | ((uint32_t)__bfloat16_as_ushort(bh) << 16);
            const __nv_bfloat16 al = __float2bfloat16(a - __bfloat162float(ah));
            const __nv_bfloat16 bl = __float2bfloat16(b2 - __bfloat162float(bh));
            ulo[k2] = (uint32_t)__bfloat16_as_ushort(al) | ((uint32_t)__bfloat16_as_ushort(bl) << 16);
        }
        uint4* dst = reinterpret_cast<uint4*>(g_xpb + pix2 * 128);
        dst[q * 2 + 0]     = make_uint4(uhi[0], uhi[1], uhi[2], uhi[3]);
        dst[q * 2 + 1]     = make_uint4(uhi[4], uhi[5], uhi[6], uhi[7]);
        dst[8 + q * 2 + 0] = make_uint4(ulo[0], ulo[1], ulo[2], ulo[3]);
        dst[8 + q * 2 + 1] = make_uint4(ulo[4], ulo[5], ulo[6], ulo[7]);
    }
}

// ---------------------------------------------------------------------------
// Kernel 2: conv via mma.sync bf16, R11 envelope (2M x 2N x 2K, 3 CTAs/SM,
// 2-slot B ring) with B-fragment reuse across A hi/lo parts in hi-B chunks:
// warp's K-split is over j2 pairs; per j2 B is loaded once, used by both parts.
// ---------------------------------------------------------------------------
constexpr int AROW = 272;                     // bytes per px slot (17 x 16B)
constexpr int AKY  = 66 * AROW;               // 17952 per raw input row
constexpr int A_RAW = 3 * AKY;                // 53856
constexpr int BROW = 144;                     // B chunk row stride (9 x 16B)
constexpr int BBUF1 = 64 * BROW;              // 9216
constexpr int CONV_SMEM = A_RAW + 2 * BBUF1;  // 72288
constexpr int SLS = 68;                       // layer_out stage stride

__device__ __forceinline__ void issue_b_chunk(uint32_t sb, int c, int tid)
{
    const int ky = c / 6, sub = c - ky * 6;
    const int var = (sub >= 3) ? 1 : 0;
    const int kx = var ? sub - 3 : sub;
    const uint32_t dst = sb + (uint32_t)((c & 1) * BBUF1);
    const __nv_bfloat16* src = g_wb + (size_t)(ky * 2 + var) * 12288 + kx * 64;
#pragma unroll
    for (int i = 0; i < 2; i++) {
        const int e = tid + i * 256;
        const int row = e >> 3, q = e & 7;
        cp16(dst + row * BROW + q * 16, src + row * 192 + q * 8);
    }
}

__global__ void __launch_bounds__(256, 3) conv_kernel(const float* __restrict__ x,
                                                      float* __restrict__ out)
{
    extern __shared__ __align__(16) char smem[];
    char* s_a = smem;
    const uint32_t sa = smem_u32(smem);
    const uint32_t sb = sa + A_RAW;

    const int tid = threadIdx.x;
    const int wid = tid >> 5, lane = tid & 31;
    const int ks = wid & 1;                      // j2-pair split
    const int wm = (wid >> 1) & 1;               // M32 half
    const int wn = wid >> 2;                     // N32 half
    const int xh = blockIdx.x;
    const int y = blockIdx.y, b = blockIdx.z;

    // ---- prologue: A (3 raw rows, halo slots) + B chunks 0,1 ----
    {
        const uint4 z = make_uint4(0, 0, 0, 0);
#pragma unroll 1
        for (int e = tid; e < 3 * 66 * 16; e += 256) {
            const int ky = e / 1056, rem = e - ky * 1056;
            const int p = rem >> 4, q = rem & 15;
            const int y2 = y + ky - 1;
            const int gx = xh * 64 + p - 1;
            const uint32_t dst = sa + (uint32_t)(ky * AKY + p * AROW + q * 16);
            if ((unsigned)y2 < 128u && (unsigned)gx < 128u)
                cp16(dst, g_xpb + (((size_t)(b * 128 + y2) * 128 + gx) * 128) + q * 8);
            else
                *reinterpret_cast<uint4*>(s_a + (ky * AKY + p * AROW + q * 16)) = z;
        }
    }
    issue_b_chunk(sb, 0, tid);
    CP_COMMIT();
    issue_b_chunk(sb, 1, tid);
    CP_COMMIT();

    float d[2][4][4];
#pragma unroll
    for (int mt = 0; mt < 2; mt++)
#pragma unroll
        for (int t = 0; t < 4; t++)
#pragma unroll
            for (int j = 0; j < 4; j++) d[mt][t][j] = 0.f;

    const uint32_t a_lane = sa + (uint32_t)((32 * wm + (lane & 15)) * AROW)
                               + (uint32_t)((lane >> 4) << 4);
    uint32_t b_lane[2];
#pragma unroll
    for (int t = 0; t < 2; t++)
        b_lane[t] = sb + (uint32_t)((32 * wn + 16 * t + (lane & 7) + ((lane >> 4) << 3)) * BROW)
                       + (uint32_t)(((lane >> 3) & 1) << 4);

#pragma unroll 1
    for (int c = 0; c < 18; c++) {
        if (c < 17) { CP_WAIT1(); } else { CP_WAIT0(); }
        __syncthreads();

        const int ky = c / 6, sub = c - ky * 6;
        const int var = (sub >= 3) ? 1 : 0;
        const int kx = var ? sub - 3 : sub;
        const uint32_t a_base = a_lane + (uint32_t)(ky * AKY + kx * AROW);
        const uint32_t b_base = (uint32_t)((c & 1) * BBUF1);

        if (!var) {
            // hi-B: this warp's j2 pair, B loaded once per (j2,t), both A parts
#pragma unroll
            for (int jj = 0; jj < 2; jj++) {
                const int j2 = 2 * ks + jj;
                uint32_t ah0[4], ah1[4], al0[4], al1[4];
                ldsm4(ah0[0], ah0[1], ah0[2], ah0[3], a_base + j2 * 32);
                ldsm4(ah1[0], ah1[1], ah1[2], ah1[3], a_base + 16 * AROW + j2 * 32);
                ldsm4(al0[0], al0[1], al0[2], al0[3], a_base + 128 + j2 * 32);
                ldsm4(al1[0], al1[1], al1[2], al1[3], a_base + 128 + 16 * AROW + j2 * 32);
#pragma unroll
                for (int t = 0; t < 2; t++) {
                    uint32_t b0, b1, b2, b3;
                    ldsm4(b0, b1, b2, b3, b_lane[t] + b_base + j2 * 32);
                    mma16816(d[0][2 * t],     ah0[0], ah0[1], ah0[2], ah0[3], b0, b1);
                    mma16816(d[0][2 * t + 1], ah0[0], ah0[1], ah0[2], ah0[3], b2, b3);
                    mma16816(d[1][2 * t],     ah1[0], ah1[1], ah1[2], ah1[3], b0, b1);
                    mma16816(d[1][2 * t + 1], ah1[0], ah1[1], ah1[2], ah1[3], b2, b3);
                    mma16816(d[0][2 * t],     al0[0], al0[1], al0[2], al0[3], b0, b1);
                    mma16816(d[0][2 * t + 1], al0[0], al0[1], al0[2], al0[3], b2, b3);
                    mma16816(d[1][2 * t],     al1[0], al1[1], al1[2], al1[3], b0, b1);
                    mma16816(d[1][2 * t + 1], al1[0], al1[1], al1[2], al1[3], b2, b3);
                }
            }
        } else {
            // lo-B: A hi part only; j2 pair split across ks (unchanged)
#pragma unroll
            for (int jj = 0; jj < 2; jj++) {
                const int j2 = 2 * ks + jj;
                uint32_t a0[4], a1[4];
                ldsm4(a0[0], a0[1], a0[2], a0[3], a_base + j2 * 32);
                ldsm4(a1[0], a1[1], a1[2], a1[3], a_base + 16 * AROW + j2 * 32);
#pragma unroll
                for (int t = 0; t < 2; t++) {
                    uint32_t b0, b1, b2, b3;
                    ldsm4(b0, b1, b2, b3, b_lane[t] + b_base + j2 * 32);
                    mma16816(d[0][2 * t],     a0[0], a0[1], a0[2], a0[3], b0, b1);
                    mma16816(d[0][2 * t + 1], a0[0], a0[1], a0[2], a0[3], b2, b3);
                    mma16816(d[1][2 * t],     a1[0], a1[1], a1[2], a1[3], b0, b1);
                    mma16816(d[1][2 * t + 1], a1[0], a1[1], a1[2], a1[3], b2, b3);
                }
            }
        }

        __syncthreads();   // slot (c&1) free for overwrite
        if (c < 16) { issue_b_chunk(sb, c + 2, tid); CP_COMMIT(); }
    }

    __syncthreads();
    // ---- layer_out partials -> smem, two copies [2][64][SLS] ----
    float* s_l = reinterpret_cast<float*>(smem);
    {
        float* dstc = s_l + ks * (64 * SLS);
        const int gid = lane >> 2, tig = lane & 3;
#pragma unroll
        for (int mt = 0; mt < 2; mt++)
#pragma unroll
            for (int t = 0; t < 2; t++)
#pragma unroll
                for (int h = 0; h < 2; h++) {
                    const int nt = 2 * t + h;
                    const int row0 = 32 * wm + 16 * mt + gid;
                    const int col = 32 * wn + 16 * t + 8 * h + 2 * tig;
                    dstc[row0 * SLS + col]           = d[mt][nt][0];
                    dstc[row0 * SLS + col + 1]       = d[mt][nt][1];
                    dstc[(row0 + 8) * SLS + col]     = d[mt][nt][2];
                    dstc[(row0 + 8) * SLS + col + 1] = d[mt][nt][3];
                }
    }
    __syncthreads();

    // ---- epilogue (vectorized): out = einsum(h_res, x) + h_post*(l0+l1) ----
    const size_t rowpix = ((size_t)b * 128 + y) * 128 + xh * 64;
    const int cq = tid & 15;
#pragma unroll 1
    for (int i = 0; i < 4; ++i) {
        const int m = i * 16 + (tid >> 4);
        const size_t pix = rowpix + m;
        const float* xp = x + pix * SCn;
        const float4* hq = reinterpret_cast<const float4*>(g_hres + pix * 16);
        float4 hr[4];
        hr[0] = hq[0]; hr[1] = hq[1]; hr[2] = hq[2]; hr[3] = hq[3];
        const float4 hpst = *reinterpret_cast<const float4*>(g_hpost + pix * 4);
        const float hpo[4] = {hpst.x, hpst.y, hpst.z, hpst.w};

        float4 xv[4];
#pragma unroll
        for (int t = 0; t < 4; t++)
            xv[t] = *reinterpret_cast<const float4*>(xp + t * 64 + cq * 4);

        const float4 l0 = *reinterpret_cast<const float4*>(s_l + m * SLS + cq * 4);
        const float4 l1 = *reinterpret_cast<const float4*>(s_l + 64 * SLS + m * SLS + cq * 4);
        const float lx = l0.x + l1.x, ly = l0.y + l1.y, lz = l0.z + l1.z, lw = l0.w + l1.w;

        float* op = out + pix * SCn;
#pragma unroll
        for (int o = 0; o < 4; o++) {
            float4 r;
            r.x = hr[o].x * xv[0].x + hr[o].y * xv[1].x + hr[o].z * xv[2].x + hr[o].w * xv[3].x + hpo[o] * lx;
            r.y = hr[o].x * xv[0].y + hr[o].y * xv[1].y + hr[o].z * xv[2].y + hr[o].w * xv[3].y + hpo[o] * ly;
            r.z = hr[o].x * xv[0].z + hr[o].y * xv[1].z + hr[o].z * xv[2].z + hr[o].w * xv[3].z + hpo[o] * lz;
            r.w = hr[o].x * xv[0].w + hr[o].y * xv[1].w + hr[o].z * xv[2].w + hr[o].w * xv[3].w + hpo[o] * lw;
            *reinterpret_cast<float4*>(op + o * 64 + cq * 4) = r;
        }
    }
}

// ---------------------------------------------------------------------------
extern "C" void kernel_launch(void* const* d_in, const int* in_sizes, int n_in,
                              void* d_out, int out_size)
{
    const float* x       = (const float*)d_in[0];
    const float* w_pre   = (const float*)d_in[1];
    const float* w_post  = (const float*)d_in[2];
    const float* w_res   = (const float*)d_in[3];
    const float* b_pre   = (const float*)d_in[4];
    const float* b_res   = (const float*)d_in[5];
    const float* b_post  = (const float*)d_in[6];
    const float* a_pre   = (const float*)d_in[7];
    const float* a_res   = (const float*)d_in[8];
    const float* a_post  = (const float*)d_in[9];
    const float* rms_w   = (const float*)d_in[10];
    const float* conv_w  = (const float*)d_in[11];
    float* out = (float*)d_out;

    cudaFuncSetAttribute(proj_kernel, cudaFuncAttributeMaxDynamicSharedMemorySize, PROJ_SMEM);
    proj_kernel<<<NPIX / 256, 256, PROJ_SMEM>>>(x, w_pre, w_post, w_res,
                                                b_pre, b_res, b_post,
                                                a_pre, a_res, a_post, rms_w, conv_w);

    cudaFuncSetAttribute(conv_kernel, cudaFuncAttributeMaxDynamicSharedMemorySize, CONV_SMEM);
    conv_kernel<<<dim3(2, Hn, Bn), 256, CONV_SMEM>>>(x, out);
}